// round 9
// baseline (speedup 1.0000x reference)
#include <cuda_runtime.h>
#include <cuda_fp16.h>
#include <cstdint>

// GraphAttentionLayer B=8,T=2048,D=256 — fp16 mma.sync, 512-thread CTAs.
//  K1: h = x@W^T, split-3 fp16, cp.async staging (measured best)
//  K2: attention, round-5 pipeline (4-stage ring, K-chunk 64) with
//      separable-exp w generation: w = sel(E2p>tau) of up*E2p / un*E2n.

#define B_ 8
#define T_ 2048
#define NEG_SLOPE 0.2f

__device__ __half g_h[B_ * T_ * 256];   // [b][j][o], 8 MB
__device__ float g_s1[B_ * T_];
__device__ float g_s2[B_ * T_];

// ---------------- helpers ----------------------------------------------------
__device__ __forceinline__ uint32_t smem_u32(const void* p) {
  uint32_t a;
  asm("{ .reg .u64 t; cvta.to.shared.u64 t, %1; cvt.u32.u64 %0, t; }"
      : "=r"(a) : "l"(p));
  return a;
}
__device__ __forceinline__ void ldsm4(uint32_t addr, uint32_t r[4]) {
  asm volatile("ldmatrix.sync.aligned.m8n8.x4.shared.b16 {%0,%1,%2,%3}, [%4];"
               : "=r"(r[0]), "=r"(r[1]), "=r"(r[2]), "=r"(r[3]) : "r"(addr));
}
__device__ __forceinline__ void ldsm4t(uint32_t addr, uint32_t r[4]) {
  asm volatile("ldmatrix.sync.aligned.m8n8.x4.trans.shared.b16 {%0,%1,%2,%3}, [%4];"
               : "=r"(r[0]), "=r"(r[1]), "=r"(r[2]), "=r"(r[3]) : "r"(addr));
}
__device__ __forceinline__ void mma16816(float c[4], const uint32_t a[4],
                                         uint32_t b0, uint32_t b1) {
  asm volatile(
      "mma.sync.aligned.m16n8k16.row.col.f32.f16.f16.f32 "
      "{%0,%1,%2,%3}, {%4,%5,%6,%7}, {%8,%9}, {%0,%1,%2,%3};"
      : "+f"(c[0]), "+f"(c[1]), "+f"(c[2]), "+f"(c[3])
      : "r"(a[0]), "r"(a[1]), "r"(a[2]), "r"(a[3]), "r"(b0), "r"(b1));
}
__device__ __forceinline__ void cpa16(uint32_t dst, const void* src) {
  asm volatile("cp.async.cg.shared.global [%0], [%1], 16;" :: "r"(dst), "l"(src)
               : "memory");
}
#define CP_COMMIT() asm volatile("cp.async.commit_group;" ::: "memory")
#define CP_WAIT(n) asm volatile("cp.async.wait_group %0;" :: "n"(n) : "memory")

// split 8 fp32 -> hi,lo fp16x8
__device__ __forceinline__ void split8(const float* v, uint4& hi, uint4& lo) {
  uint32_t h[4], l[4];
#pragma unroll
  for (int q = 0; q < 4; q++) {
    float a = v[2 * q], b = v[2 * q + 1];
    __half ah = __float2half_rn(a), bh = __float2half_rn(b);
    __half2 hv; hv.x = ah; hv.y = bh; h[q] = *(uint32_t*)&hv;
    __half2 lv;
    lv.x = __float2half_rn(a - __half2float(ah));
    lv.y = __float2half_rn(b - __half2float(bh));
    l[q] = *(uint32_t*)&lv;
  }
  hi = make_uint4(h[0], h[1], h[2], h[3]);
  lo = make_uint4(l[0], l[1], l[2], l[3]);
}

// ============================================================================
// K1: h = x @ W^T. 128 CTAs, 512 threads, warp grid 4x4 (warp tile 32x64).
// K=256 in 4 chunks of 64. Split-3 fp16. cp.async fp32 staging, overlapped.
// ============================================================================
#define K1_FX 0                    // fp32 x tile [128][68]
#define K1_FW 34816                // fp32 W tile [256][68]
#define K1_AH 104448               // [128][72] fp16
#define K1_AL 122880
#define K1_BH 141312               // [256][72] fp16
#define K1_BL 178176
#define K1_AS 215040               // a[512] f32
#define K1_R1 217088               // [4][128] f32
#define K1_R2 219136
#define K1_SMEM 221184

__global__ __launch_bounds__(512, 1) void k1(
    const float* __restrict__ x, const float* __restrict__ W,
    const float* __restrict__ a) {
  extern __shared__ char sm[];
  const uint32_t SB = smem_u32(sm);
  const int t = threadIdx.x, lane = t & 31, wid = t >> 5;
  const int warpM = wid >> 2, warpN = wid & 3;
  const int i0 = blockIdx.x * 128;

#define K1_LOADF32(cc) do {                                                   \
    const int k0_ = (cc) * 64;                                                \
    _Pragma("unroll")                                                         \
    for (int v = 0; v < 4; v++) {                                             \
      int u = v * 512 + t, row = u >> 4, seg = u & 15;                        \
      cpa16(SB + K1_FX + (uint32_t)(row * 68 + seg * 4) * 4,                  \
            &x[(size_t)(i0 + row) * 256 + k0_ + seg * 4]);                    \
    }                                                                         \
    _Pragma("unroll")                                                         \
    for (int v = 0; v < 8; v++) {                                             \
      int u = v * 512 + t, row = u >> 4, seg = u & 15;                        \
      cpa16(SB + K1_FW + (uint32_t)(row * 68 + seg * 4) * 4,                  \
            &W[(size_t)row * 256 + k0_ + seg * 4]);                           \
    }                                                                         \
  } while (0)

  K1_LOADF32(0);
  CP_COMMIT();
  ((float*)(sm + K1_AS))[t] = a[t];

  float c[2][8][4];
#pragma unroll
  for (int r = 0; r < 2; r++)
#pragma unroll
    for (int f = 0; f < 8; f++)
#pragma unroll
      for (int q = 0; q < 4; q++) c[r][f][q] = 0.f;

  CP_WAIT(0);
  __syncthreads();

  for (int ch = 0; ch < 4; ch++) {
    // convert fp32 staging -> fp16 hi/lo tiles
    {
      const int row = t >> 2, quad = t & 3;
      float v[16];
#pragma unroll
      for (int q = 0; q < 4; q++)
        *(float4*)&v[q * 4] =
            *(const float4*)(sm + K1_FX + (uint32_t)(row * 68 + quad * 16 + q * 4) * 4);
      uint4 h0, l0, h1, l1;
      split8(v, h0, l0); split8(v + 8, h1, l1);
      const uint32_t off = (uint32_t)(row * 72 + quad * 16) * 2;
      *(uint4*)(sm + K1_AH + off) = h0; *(uint4*)(sm + K1_AH + off + 16) = h1;
      *(uint4*)(sm + K1_AL + off) = l0; *(uint4*)(sm + K1_AL + off + 16) = l1;
    }
    {
      const int row = t >> 1, half = (t & 1) * 32;
      float v[32];
#pragma unroll
      for (int q = 0; q < 8; q++)
        *(float4*)&v[q * 4] =
            *(const float4*)(sm + K1_FW + (uint32_t)(row * 68 + half + q * 4) * 4);
      const uint32_t off = (uint32_t)(row * 72 + half) * 2;
#pragma unroll
      for (int g = 0; g < 4; g++) {
        uint4 hh, ll;
        split8(v + g * 8, hh, ll);
        *(uint4*)(sm + K1_BH + off + g * 16) = hh;
        *(uint4*)(sm + K1_BL + off + g * 16) = ll;
      }
    }
    __syncthreads();
    if (ch < 3) { K1_LOADF32(ch + 1); CP_COMMIT(); }

#pragma unroll
    for (int ks = 0; ks < 64; ks += 16) {
      const uint32_t lrow = (uint32_t)(lane & 15);
      const uint32_t lcol = (uint32_t)(ks + ((lane >> 4) << 3));
      uint32_t ah[2][4], al[2][4];
#pragma unroll
      for (int r = 0; r < 2; r++) {
        uint32_t ra = SB + ((warpM * 32 + r * 16 + lrow) * 72 + lcol) * 2;
        ldsm4(ra + K1_AH, ah[r]);
        ldsm4(ra + K1_AL, al[r]);
      }
      uint32_t bh[8][2], bl[8][2];
#pragma unroll
      for (int q = 0; q < 4; q++) {
        uint32_t rb = SB + ((warpN * 64 + q * 16 + lrow) * 72 + lcol) * 2;
        uint32_t rr[4];
        ldsm4(rb + K1_BH, rr);
        bh[2 * q][0] = rr[0]; bh[2 * q + 1][0] = rr[1];
        bh[2 * q][1] = rr[2]; bh[2 * q + 1][1] = rr[3];
        ldsm4(rb + K1_BL, rr);
        bl[2 * q][0] = rr[0]; bl[2 * q + 1][0] = rr[1];
        bl[2 * q][1] = rr[2]; bl[2 * q + 1][1] = rr[3];
      }
#pragma unroll
      for (int r = 0; r < 2; r++)
#pragma unroll
        for (int f = 0; f < 8; f++) mma16816(c[r][f], ah[r], bh[f][0], bh[f][1]);
#pragma unroll
      for (int r = 0; r < 2; r++)
#pragma unroll
        for (int f = 0; f < 8; f++) mma16816(c[r][f], ah[r], bl[f][0], bl[f][1]);
#pragma unroll
      for (int r = 0; r < 2; r++)
#pragma unroll
        for (int f = 0; f < 8; f++) mma16816(c[r][f], al[r], bh[f][0], bh[f][1]);
    }
    CP_WAIT(0);
    __syncthreads();
  }

  // ---- epilogue: s1/s2 partials + h fp16 stores ----
  const float* as_ = (const float*)(sm + K1_AS);
  float s1p[4], s2p[4];
#pragma unroll
  for (int q = 0; q < 4; q++) { s1p[q] = 0.f; s2p[q] = 0.f; }
#pragma unroll
  for (int r = 0; r < 2; r++)
#pragma unroll
    for (int f = 0; f < 8; f++)
#pragma unroll
      for (int q = 0; q < 4; q++) {
        int col = warpN * 64 + f * 8 + 2 * (lane & 3) + (q & 1);
        int ri = r * 2 + (q >> 1);
        s1p[ri] += c[r][f][q] * as_[col];
        s2p[ri] += c[r][f][q] * as_[256 + col];
      }
#pragma unroll
  for (int o = 1; o < 4; o <<= 1)
#pragma unroll
    for (int ri = 0; ri < 4; ri++) {
      s1p[ri] += __shfl_xor_sync(0xffffffffu, s1p[ri], o);
      s2p[ri] += __shfl_xor_sync(0xffffffffu, s2p[ri], o);
    }
  if ((lane & 3) == 0) {
#pragma unroll
    for (int r = 0; r < 2; r++)
#pragma unroll
      for (int hh = 0; hh < 2; hh++) {
        int rowr = warpM * 32 + r * 16 + (lane >> 2) + hh * 8;
        ((float*)(sm + K1_R1))[warpN * 128 + rowr] = s1p[r * 2 + hh];
        ((float*)(sm + K1_R2))[warpN * 128 + rowr] = s2p[r * 2 + hh];
      }
  }
#pragma unroll
  for (int r = 0; r < 2; r++)
#pragma unroll
    for (int f = 0; f < 8; f++) {
      int row0 = i0 + warpM * 32 + r * 16 + (lane >> 2);
      int col0 = warpN * 64 + f * 8 + 2 * (lane & 3);
#pragma unroll
      for (int hh = 0; hh < 2; hh++) {
        size_t base = (size_t)(row0 + hh * 8) * 256 + col0;
        __half2 ph;
        ph.x = __float2half_rn(c[r][f][hh * 2]);
        ph.y = __float2half_rn(c[r][f][hh * 2 + 1]);
        *(uint32_t*)&g_h[base] = *(uint32_t*)&ph;
      }
    }
  __syncthreads();
  if (t < 128) {
    const float* r1 = (const float*)(sm + K1_R1);
    const float* r2 = (const float*)(sm + K1_R2);
    float v1 = 0.f, v2 = 0.f;
#pragma unroll
    for (int wn = 0; wn < 4; wn++) { v1 += r1[wn * 128 + t]; v2 += r2[wn * 128 + t]; }
    g_s1[i0 + t] = v1;
    g_s2[i0 + t] = v2;
  }
}

// ============================================================================
// K2: attention. 128 CTAs, 512 threads, warp grid 4x4 (warp tile 32x64).
// CTA M=128, N=256, K=2048 in 32 chunks of 64. 4-stage cp.async ring
// (round-5 structure); separable-exp w generation:
//   w(i,j) = (E2p[j] > tau_i) ? up_i*E2p[j] : un_i*E2n[j]
// with E2p=exp(s2), E2n=exp(.2 s2), up=exp(s1), un=exp(.2 s1), tau=exp(-s1).
// Denominator sums the fp16-rounded w (consistent with numerator).
// ============================================================================
#define ATB 0                     // 4 stages x [64][264] fp16
#define ATB_STG 33792
#define AT_A 135168               // 2 x [128][72] fp16
#define AT_AST 18432
#define AT_E2 172032              // float2[2048] = 16384
#define AT_S1 188416              // 128 f32
#define AT_DB 188928              // 512 f32
#define AT_DEN 190976             // 128 f32
#define AT_SMEM 191488

__global__ __launch_bounds__(512, 1) void k2(float* __restrict__ out) {
  extern __shared__ char sm[];
  const uint32_t SB = smem_u32(sm);
  const int t = threadIdx.x, lane = t & 31, wid = t >> 5;
  const int warpM = wid >> 2, warpN = wid & 3;
  const int b = blockIdx.x >> 4;
  const int i0 = (blockIdx.x & 15) * 128;

  // prologue tables: E2p/E2n per j; s1 per row
  if (t < 128) ((float*)(sm + AT_S1))[t] = g_s1[b * 2048 + i0 + t];
#pragma unroll
  for (int j = t; j < 2048; j += 512) {
    float s2v = g_s2[b * 2048 + j];
    ((float2*)(sm + AT_E2))[j] = make_float2(__expf(s2v), __expf(NEG_SLOPE * s2v));
  }
  __syncthreads();

  const float* e2s = (const float*)(sm + AT_E2);
  const int gm = t >> 2, gkh = (t & 3) * 16;   // w-gen: row gm, cols gkh..+15
  const float s1v = ((const float*)(sm + AT_S1))[gm];
  const float up = __expf(s1v);
  const float un = __expf(NEG_SLOPE * s1v);
  const float tau = __expf(-s1v);
  const __half* H = g_h + (size_t)b * 2048 * 256;

  float c[2][8][4];
#pragma unroll
  for (int r = 0; r < 2; r++)
#pragma unroll
    for (int f = 0; f < 8; f++)
#pragma unroll
      for (int q = 0; q < 4; q++) c[r][f][q] = 0.f;
  float dtot = 0.f;

#define GENW(nn, abuf) do {                                                   \
    const int jb_ = (nn) * 64 + gkh;                                          \
    uint32_t pkk[8];                                                          \
_Pragma("unroll")                                                             \
    for (int q = 0; q < 8; q++) {                                             \
      float4 e = *(const float4*)&e2s[2 * (jb_ + 2 * q)];                     \
      float w0 = (e.x > tau) ? up * e.x : un * e.y;                           \
      float w1 = (e.z > tau) ? up * e.z : un * e.w;                           \
      __half h0 = __float2half_rn(w0);                                        \
      __half h1 = __float2half_rn(w1);                                        \
      dtot += __half2float(h0) + __half2float(h1);                            \
      __half2 pp; pp.x = h0; pp.y = h1;                                       \
      pkk[q] = *(uint32_t*)&pp;                                               \
    }                                                                         \
    const uint32_t off_ = (uint32_t)(gm * 72 + gkh) * 2;                      \
    *(uint4*)((abuf) + off_) = make_uint4(pkk[0], pkk[1], pkk[2], pkk[3]);    \
    *(uint4*)((abuf) + off_ + 16) = make_uint4(pkk[4], pkk[5], pkk[6], pkk[7]); \
  } while (0)

#define LOADB(nn) do {                                                        \
    const uint32_t dst_ = SB + ATB + ((nn) & 3) * ATB_STG;                    \
    const int j0_ = (nn) * 64;                                                \
_Pragma("unroll")                                                             \
    for (int v = 0; v < 4; v++) {                                             \
      int u = v * 512 + t, row = u >> 5, seg = u & 31;                        \
      cpa16(dst_ + (uint32_t)(row * 264 + seg * 8) * 2,                       \
            H + (size_t)(j0_ + row) * 256 + seg * 8);                         \
    }                                                                         \
  } while (0)

  // prologue
  GENW(0, sm + AT_A);
#pragma unroll
  for (int pc = 0; pc < 3; pc++) { LOADB(pc); CP_COMMIT(); }
  CP_WAIT(2);
  __syncthreads();

  for (int n = 0; n < 32; n++) {
    const int p = n & 1;
    const uint32_t Bst = SB + ATB + (n & 3) * ATB_STG;
    const uint32_t Ab = SB + AT_A + p * AT_AST;

    // mma chunk n
#pragma unroll
    for (int ks = 0; ks < 64; ks += 16) {
      uint32_t ah[2][4];
#pragma unroll
      for (int r = 0; r < 2; r++)
        ldsm4(Ab + ((warpM * 32 + r * 16 + (lane & 15)) * 72 + ks +
                    ((lane >> 4) << 3)) * 2,
              ah[r]);
      const uint32_t roff =
          (uint32_t)(ks + ((lane >> 3) & 1) * 8 + (lane & 7)) * 264;
      uint32_t bh[8][2];
#pragma unroll
      for (int q = 0; q < 4; q++) {
        uint32_t coff = (uint32_t)(warpN * 64 + q * 16 + ((lane >> 4) << 3));
        uint32_t rr[4];
        ldsm4t(Bst + (roff + coff) * 2, rr);
        bh[2 * q][0] = rr[0]; bh[2 * q][1] = rr[1];
        bh[2 * q + 1][0] = rr[2]; bh[2 * q + 1][1] = rr[3];
      }
#pragma unroll
      for (int r = 0; r < 2; r++)
#pragma unroll
        for (int f = 0; f < 8; f++) mma16816(c[r][f], ah[r], bh[f][0], bh[f][1]);
    }

    // overlap: gen w for chunk n+1 into other A buffer, prefetch chunk n+3
    if (n < 31) GENW(n + 1, sm + AT_A + (p ^ 1) * AT_AST);
    if (n + 3 < 32) LOADB(n + 3);
    CP_COMMIT();
    CP_WAIT(2);
    __syncthreads();
  }

  // ---- denominator + epilogue ----
  ((float*)(sm + AT_DB))[t] = dtot;
  __syncthreads();
  if (t < 128) {
    const float* db = (const float*)(sm + AT_DB);
    ((float*)(sm + AT_DEN))[t] =
        db[4 * t] + db[4 * t + 1] + db[4 * t + 2] + db[4 * t + 3];
  }
  __syncthreads();
  const float* den = (const float*)(sm + AT_DEN);
  float inv[4];
#pragma unroll
  for (int r = 0; r < 2; r++)
#pragma unroll
    for (int hh = 0; hh < 2; hh++)
      inv[r * 2 + hh] =
          1.0f / den[warpM * 32 + r * 16 + (lane >> 2) + hh * 8];

  float* ob = out + ((size_t)b * 2048 + i0) * 256;
#pragma unroll
  for (int r = 0; r < 2; r++)
#pragma unroll
    for (int f = 0; f < 8; f++) {
      int col = warpN * 64 + f * 8 + 2 * (lane & 3);
#pragma unroll
      for (int hh = 0; hh < 2; hh++) {
        int row = warpM * 32 + r * 16 + (lane >> 2) + hh * 8;
        float iv = inv[r * 2 + hh];
        float v0 = c[r][f][hh * 2] * iv;
        float v1 = c[r][f][hh * 2 + 1] * iv;
        v0 = v0 > 0.f ? v0 : expm1f(v0);
        v1 = v1 > 0.f ? v1 : expm1f(v1);
        *(float2*)&ob[(size_t)row * 256 + col] = make_float2(v0, v1);
      }
    }
}

// ============================================================================
extern "C" void kernel_launch(void* const* d_in, const int* in_sizes, int n_in,
                              void* d_out, int out_size) {
  (void)in_sizes; (void)n_in; (void)out_size;
  const float* x = (const float*)d_in[0];
  const float* W = (const float*)d_in[1];
  const float* a = (const float*)d_in[2];
  float* out = (float*)d_out;

  cudaFuncSetAttribute(k1, cudaFuncAttributeMaxDynamicSharedMemorySize, K1_SMEM);
  cudaFuncSetAttribute(k2, cudaFuncAttributeMaxDynamicSharedMemorySize, AT_SMEM);

  k1<<<128, 512, K1_SMEM>>>(x, W, a);
  k2<<<128, 512, AT_SMEM>>>(out);
}